// round 10
// baseline (speedup 1.0000x reference)
#include <cuda_runtime.h>
#include <cstdint>
#include <mma.h>
#include <math.h>

using namespace nvcuda;

#define B_   4
#define T_   4096
#define D_   1024
#define H_   8
#define BS_  128
#define SC_  32              /* timesteps per GEMM sub-chunk */
#define NLNK_ 3              /* time links */
#define L01_ 1376            /* steps in links 0,1 (43 subchunks) */
#define L2_  1344            /* steps in link 2 (42 subchunks) */
#define NCB_ 32              /* channel-blocks: H * 4 quarters */
#define WP_  36              /* weight tile row stride */
#define ZPT_ 36              /* z tile (channel-major) row stride */
#define XP_  132             /* x tile row stride */

// Scratch (device globals; no allocation allowed). No flags, no spins.
__device__ __align__(16) float g_ylocal[B_*T_*D_];   /* links 1,2 only */
__device__ __align__(16) float g_prefix[B_*T_*D_];
__device__ __align__(16) float g_S0end[B_*D_];       /* state after link 0 */
__device__ __align__(16) float g_lP[2*B_*D_];        /* A-product, links 1,2 */
__device__ __align__(16) float g_lY[2*B_*D_];        /* local Y, links 1,2 */
__device__ __align__(16) float g_C[2*B_*D_];         /* carries into links 1,2 */

// smem layout (floats) — single x buffer
#define OFF_W1   0
#define OFF_W2   (OFF_W1 + 128*WP_)     /* 4608  */
#define OFF_XS   (OFF_W2 + 128*WP_)     /* 9216  */
#define OFF_Z1   (OFF_XS + SC_*XP_)     /* 13440 */
#define OFF_Z2   (OFF_Z1 + 32*ZPT_)     /* 14592 */
#define OFF_SPS  (OFF_Z2 + 32*ZPT_)     /* 15744 */
#define SMEM_FLOATS (OFF_SPS + 32)      /* 15776 -> 61.6 KB -> 3 CTAs/SM */
#define SMEM_BYTES  (SMEM_FLOATS*4)

__device__ __forceinline__ void cp16(unsigned dst, const float* src) {
    asm volatile("cp.async.cg.shared.global [%0], [%1], 16;" :: "r"(dst), "l"(src));
}

// ---------------------------------------------------------------------------
// K1: block = (link, channel-block, batch). 32 channels, ~1376 steps.
// 384 blocks, 3 CTAs/SM, one wave, zero inter-block communication.
// ---------------------------------------------------------------------------
__global__ void __launch_bounds__(256, 3) k1_gemm_scan(
    const float* __restrict__ x, const float* __restrict__ a_param,
    const float* __restrict__ w_in, const float* __restrict__ w_a,
    float* __restrict__ out)
{
    extern __shared__ float sm[];
    float* w1s = sm + OFF_W1;
    float* w2s = sm + OFF_W2;
    float* xs  = sm + OFF_XS;
    float* z1  = sm + OFF_Z1;    // [32 ch][ZPT_] gate_x z (channel-major)
    float* z2  = sm + OFF_Z2;    // [32 ch][ZPT_] gate_a z
    float* sps = sm + OFF_SPS;

    const int b    = blockIdx.z;
    const int cb   = blockIdx.y;
    const int h    = cb >> 2;
    const int q    = cb & 3;
    const int gb   = blockIdx.x;          // 0,1,2
    const int tid  = threadIdx.x;
    const int col0 = h*BS_ + q*32;
    const int t0   = gb*L01_;
    const int nsc  = (gb < 2) ? (L01_/SC_) : (L2_/SC_);

    // Stage weights (32 output cols of both gates), tf32 pre-rounded
    {
        const float* w1g = w_in + (size_t)h*BS_*BS_ + q*32;
        const float* w2g = w_a  + (size_t)h*BS_*BS_ + q*32;
        for (int i = tid; i < 128*32; i += 256) {
            int d = i >> 5, e = i & 31;
            w1s[d*WP_ + e] = wmma::__float_to_tf32(w1g[d*BS_ + e]);
            w2s[d*WP_ + e] = wmma::__float_to_tf32(w2g[d*BS_ + e]);
        }
        if (tid < 32) {
            float apv = a_param[col0 + tid];
            sps[tid]  = 8.0f * log1pf(__expf(apv));   // C * softplus(a_param)
        }
    }

    const int warp = tid >> 5;
    const int lane = tid & 31;
    // GEMM mapping
    const int g    = warp >> 2;        // gate 0/1
    const int rb   = (warp >> 1) & 1;  // 16-row block of M=32
    const int cq   = warp & 1;         // 16-col half of N=32
    float* wg = g ? w2s : w1s;
    float* zg = g ? z2  : z1;
    // scan mapping: lane = el*8 + sg ; channel e = warp*4 + el
    const int el = lane >> 3;
    const int sg = lane & 7;
    const int e  = warp*4 + el;

    const float* xg_base = x + ((size_t)(b*T_ + t0))*D_ + h*BS_;
    const unsigned xsb = (unsigned)__cvta_generic_to_shared(xs);

    __syncthreads();
    const float spe = sps[e];

    float s_sub = 0.0f;   // block-relative state
    float P_sub = 1.0f;   // running prefix product

    for (int cc = 0; cc < nsc; ++cc) {
        const int ts = cc*SC_;    // block-relative first timestep

        // ---- stage x tile [SC_][128] (single buffer) ----
        {
            const float* xg = xg_base + (size_t)ts*D_;
            #pragma unroll
            for (int k = 0; k < 4; ++k) {
                int qq = tid + 256*k;
                int t  = qq >> 5, c4 = (qq & 31) << 2;
                cp16(xsb + (unsigned)(t*XP_ + c4)*4u, xg + (size_t)t*D_ + c4);
            }
            asm volatile("cp.async.commit_group;");
            asm volatile("cp.async.wait_group 0;");
        }
        __syncthreads();   // tile visible

        // ---- GEMM: M=32, N=32, K=128; warps split across gates ----
        {
            wmma::fragment<wmma::accumulator, 16, 16, 8, float> acc;
            wmma::fill_fragment(acc, 0.0f);
            const float* xb = xs + rb*16*XP_;
            #pragma unroll 4
            for (int kk = 0; kk < 16; ++kk) {
                wmma::fragment<wmma::matrix_a, 16, 16, 8, wmma::precision::tf32, wmma::row_major> af;
                wmma::load_matrix_sync(af, xb + kk*8, XP_);
                #pragma unroll
                for (int i = 0; i < af.num_elements; ++i) af.x[i] = wmma::__float_to_tf32(af.x[i]);
                wmma::fragment<wmma::matrix_b, 16, 16, 8, wmma::precision::tf32, wmma::row_major> bf;
                wmma::load_matrix_sync(bf, wg + kk*8*WP_ + cq*16, WP_);
                wmma::mma_sync(acc, af, bf, acc);
            }
            // channel-major store: z[e][t]
            wmma::store_matrix_sync(zg + (cq*16)*ZPT_ + rb*16, acc, ZPT_, wmma::mem_col_major);
        }
        __syncthreads();

        // ---- scan lane work: 1 channel x 4 timesteps ----
        {
            const float4 zx4 = *reinterpret_cast<const float4*>(z1 + e*ZPT_ + sg*4);
            const float4 za4 = *reinterpret_cast<const float4*>(z2 + e*ZPT_ + sg*4);
            const float* xvp = xs + (sg*4)*XP_ + q*32 + e;

            float av[4], bv[4];
            float Pseg = 1.0f, Yseg = 0.0f;
            const float zx[4] = {zx4.x, zx4.y, zx4.z, zx4.w};
            const float za[4] = {za4.x, za4.y, za4.z, za4.w};
            #pragma unroll
            for (int i = 0; i < 4; ++i) {
                float gi = __fdividef(1.0f, 1.0f + __expf(-zx[i]));
                float ga = __fdividef(1.0f, 1.0f + __expf(-za[i]));
                float la = -spe * ga;
                float a  = __expf(la);
                float m2 = -expm1f(2.0f*la);          // 1 - exp(2*la), accurate
                float mult = sqrtf(fmaxf(m2, 0.0f));
                float bb = mult * gi * xvp[i*XP_];
                av[i] = a; bv[i] = bb;
                Yseg = fmaf(a, Yseg, bb);
                Pseg *= a;
            }
            // Kogge-Stone over 8 segments (width-8 shuffles)
            float Ac = Pseg, Yc = Yseg;
            #pragma unroll
            for (int d = 1; d < 8; d <<= 1) {
                float Ap = __shfl_up_sync(0xffffffffu, Ac, d, 8);
                float Yp = __shfl_up_sync(0xffffffffu, Yc, d, 8);
                if (sg >= d) { Yc = fmaf(Ac, Yp, Yc); Ac *= Ap; }
            }
            float Aex = __shfl_up_sync(0xffffffffu, Ac, 1, 8);
            float Yex = __shfl_up_sync(0xffffffffu, Yc, 1, 8);
            if (sg == 0) { Aex = 1.0f; Yex = 0.0f; }
            const float At = __shfl_sync(0xffffffffu, Ac, 7, 8);
            const float Yt = __shfl_sync(0xffffffffu, Yc, 7, 8);

            float s = fmaf(Aex, s_sub, Yex);
            float P = P_sub * Aex;
            const size_t gbase = ((size_t)(b*T_ + t0 + ts + sg*4))*D_ + col0 + e;
            if (gb == 0) {
                #pragma unroll
                for (int i = 0; i < 4; ++i) {
                    s = fmaf(av[i], s, bv[i]);
                    out[gbase + (size_t)i*D_] = s;    // carry-in is 0: y == local
                }
            } else {
                #pragma unroll
                for (int i = 0; i < 4; ++i) {
                    s = fmaf(av[i], s, bv[i]);
                    P *= av[i];
                    g_ylocal[gbase + (size_t)i*D_] = s;
                    g_prefix[gbase + (size_t)i*D_] = P;
                }
            }
            s_sub = fmaf(At, s_sub, Yt);
            P_sub *= At;
        }
        __syncthreads();   // scan done; x/z reusable next iter
    }

    // publish summaries (no waiting, no flags)
    if (sg == 0) {
        const int gi = b*D_ + col0 + e;
        if (gb == 0) {
            g_S0end[gi] = s_sub;              // state entering link 1
        } else {
            g_lP[(gb-1)*B_*D_ + gi] = P_sub;
            g_lY[(gb-1)*B_*D_ + gi] = s_sub;
        }
    }
}

// ---------------------------------------------------------------------------
// K2: 3-link combine per channel -> carries + h_last
// ---------------------------------------------------------------------------
__global__ void k2_combine(float* __restrict__ out)
{
    int i = blockIdx.x*blockDim.x + threadIdx.x;   // 0 .. B*D-1
    float C1 = g_S0end[i];
    float C2 = fmaf(g_lP[i], C1, g_lY[i]);
    g_C[i]          = C1;
    g_C[B_*D_ + i]  = C2;
    out[(size_t)B_*T_*D_ + i] = fmaf(g_lP[B_*D_ + i], C2, g_lY[B_*D_ + i]);
}

// ---------------------------------------------------------------------------
// K3: links 1,2: y = y_local + C * prefix  (float4 streaming)
// ---------------------------------------------------------------------------
#define TREM_ (T_ - L01_)    /* 2720 */
__global__ void __launch_bounds__(256) k3_apply(float* __restrict__ out)
{
    size_t j = (size_t)blockIdx.x*256 + threadIdx.x;   // over B*TREM_*(D/4)
    int d4   = (int)(j & 255);                          // D/4 = 256
    size_t r = j >> 8;
    int tt   = (int)(r % TREM_);
    int b    = (int)(r / TREM_);
    int t    = L01_ + tt;
    int link = (tt >= L01_) ? 1 : 0;
    size_t i = ((size_t)(b*T_ + t))*D_ + d4*4;
    const float4 S  = *reinterpret_cast<const float4*>(g_C + (size_t)link*B_*D_ + b*D_ + d4*4);
    const float4 yl = *reinterpret_cast<const float4*>(g_ylocal + i);
    const float4 P  = *reinterpret_cast<const float4*>(g_prefix + i);
    float4 rr;
    rr.x = fmaf(S.x, P.x, yl.x);
    rr.y = fmaf(S.y, P.y, yl.y);
    rr.z = fmaf(S.z, P.z, yl.z);
    rr.w = fmaf(S.w, P.w, yl.w);
    *reinterpret_cast<float4*>(out + i) = rr;
}

extern "C" void kernel_launch(void* const* d_in, const int* in_sizes, int n_in,
                              void* d_out, int out_size)
{
    const float* x  = (const float*)d_in[0];
    const float* ap = (const float*)d_in[1];
    const float* wi = (const float*)d_in[2];
    const float* wa = (const float*)d_in[3];
    float* out = (float*)d_out;

    cudaFuncSetAttribute(k1_gemm_scan,
                         cudaFuncAttributeMaxDynamicSharedMemorySize, SMEM_BYTES);

    k1_gemm_scan<<<dim3(NLNK_, NCB_, B_), 256, SMEM_BYTES>>>(x, ap, wi, wa, out);
    k2_combine<<<(B_*D_)/256, 256>>>(out);
    k3_apply<<<(B_*TREM_*(D_/4))/256, 256>>>(out);
}